// round 13
// baseline (speedup 1.0000x reference)
#include <cuda_runtime.h>
#include <cuda_bf16.h>
#include <cstdint>

#define B_   64
#define T_   4096
#define IN_  32
#define H_   128
#define G_   384
#define OUT_ 32
#define BT_  (B_ * T_)
#define GDEPTH 8          // cp.async gi ring depth
#define NWRK 24           // gi1 GEMM worker CTAs (grid 152 = GB300 SM count)
#define CHUNK 64          // pipeline chunk (steps)

// worker SMEM geometry
#define APAD 132          // A row stride (floats): 64 rows x 132
#define BPAD 100          // B row stride (floats): 16 rows x 100, double buffered
#define POOLF (64 * APAD + 2 * 16 * BPAD + 64)   // 11712 floats; >= scan pool (7712)

// ---------------- scratch (static __device__; allocation-free rule) ----------
__device__ float g_gi [(size_t)BT_ * G_];    // layer-0 gate pre-activations
__device__ float g_gi1[(size_t)BT_ * G_];    // layer-1 gate pre-activations
__device__ float g_y0 [(size_t)BT_ * H_];    // layer-0 outputs
__device__ unsigned g_flag0[B_];             // y0 rows ready per batch
__device__ unsigned g_flag1[B_];             // gi1 rows ready per batch

typedef unsigned long long u64t;

// ---------------- packed f32x2 helpers (sm_103a FFMA2 via PTX) ---------------
__device__ __forceinline__ u64t pk2(float a, float b) {
    u64t r; asm("mov.b64 %0, {%1,%2};" : "=l"(r) : "f"(a), "f"(b)); return r;
}
__device__ __forceinline__ u64t fma2(u64t a, u64t b, u64t c) {
    u64t d; asm("fma.rn.f32x2 %0, %1, %2, %3;" : "=l"(d) : "l"(a), "l"(b), "l"(c)); return d;
}
__device__ __forceinline__ u64t add2(u64t a, u64t b) {
    u64t d; asm("add.rn.f32x2 %0, %1, %2;" : "=l"(d) : "l"(a), "l"(b)); return d;
}
__device__ __forceinline__ float2 upk2(u64t a) {
    float2 f; asm("mov.b64 {%0,%1}, %2;" : "=f"(f.x), "=f"(f.y) : "l"(a)); return f;
}

__device__ __forceinline__ float sigmf(float x) {
    return __fdividef(1.f, 1.f + __expf(-x));
}
__device__ __forceinline__ float tanhfast(float x) {
    float e = __expf(-2.f * x);
    return __fdividef(1.f - e, 1.f + e);
}

__device__ __forceinline__ uint32_t smem_u32(const void* p) {
    uint32_t a;
    asm("{ .reg .u64 t; cvta.to.shared.u64 t, %1; cvt.u32.u64 %0, t; }"
        : "=r"(a) : "l"(p));
    return a;
}
__device__ __forceinline__ void cp_async4(uint32_t saddr, const float* gaddr) {
    asm volatile("cp.async.ca.shared.global [%0], [%1], 4;" :: "r"(saddr), "l"(gaddr));
}
__device__ __forceinline__ void cp_async16(uint32_t saddr, const float* gaddr) {
    asm volatile("cp.async.ca.shared.global [%0], [%1], 16;" :: "r"(saddr), "l"(gaddr));
}
__device__ __forceinline__ void cp_commit() { asm volatile("cp.async.commit_group;"); }
__device__ __forceinline__ void cp_wait7()  { asm volatile("cp.async.wait_group 7;"); }
__device__ __forceinline__ void cp_wait0()  { asm volatile("cp.async.wait_group 0;"); }

__device__ __forceinline__ unsigned ld_acq(const unsigned* p) {
    unsigned v;
    asm volatile("ld.acquire.gpu.global.u32 %0, [%1];" : "=r"(v) : "l"(p) : "memory");
    return v;
}
__device__ __forceinline__ void st_rel(unsigned* p, unsigned v) {
    asm volatile("st.release.gpu.global.u32 [%0], %1;" :: "l"(p), "r"(v) : "memory");
}
__device__ __forceinline__ void npause() {
    asm volatile("nanosleep.u32 200;");
}

// ============================================================================
// K1: gi0 = x @ W_ih0^T + b_ih0 (64 rows/CTA; also resets flags each replay)
// ============================================================================
__global__ void k1_gi0(const float* __restrict__ x,
                       const float* __restrict__ W,
                       const float* __restrict__ b) {
    __shared__ __align__(16) float sx[64 * IN_];
    const int tid = threadIdx.x;                 // gate row 0..383
    const size_t bt0 = (size_t)blockIdx.x * 64;

    if (blockIdx.x == 0 && tid < 2 * B_) {
        if (tid < B_) g_flag0[tid] = 0; else g_flag1[tid - B_] = 0;
    }

    for (int i = tid; i < 64 * IN_ / 4; i += 384)
        ((float4*)sx)[i] = ((const float4*)(x + bt0 * IN_))[i];

    u64t wp[16];
    {
        const float4* wr = (const float4*)(W + (size_t)tid * IN_);
#pragma unroll
        for (int q = 0; q < 8; q++) {
            float4 w4 = __ldg(wr + q);
            wp[2 * q]     = pk2(w4.x, w4.y);
            wp[2 * q + 1] = pk2(w4.z, w4.w);
        }
    }
    const float bias = __ldg(b + tid);
    __syncthreads();

#pragma unroll 4
    for (int row = 0; row < 64; row++) {
        const ulonglong2* xr = (const ulonglong2*)(sx + row * IN_);
        u64t a0 = 0ull, a1 = 0ull;
#pragma unroll
        for (int q = 0; q < 8; q++) {
            ulonglong2 xp = xr[q];
            a0 = fma2(wp[2 * q],     xp.x, a0);
            a1 = fma2(wp[2 * q + 1], xp.y, a1);
        }
        float2 s = upk2(add2(a0, a1));
        g_gi[(bt0 + row) * G_ + tid] = s.x + s.y + bias;
    }
}

// ============================================================================
// Worker role (R12-proven, frozen): gi1[b, c*64 .. c*64+64) = y0 @ W_ih1^T + b.
// ============================================================================
__device__ __forceinline__ void worker_role(
    int w, const float* __restrict__ W, const float* __restrict__ bias,
    float* __restrict__ pool)
{
    float* sA = pool;                        // 64 x APAD
    float* sB = pool + 64 * APAD;            // 2 x 16 x BPAD

    const int tid = threadIdx.x;
    const int tx = tid % 24, ty = tid / 24;  // 24 x 16 -> C tile 64m x 96n
    const int gg = tid >> 2, kq4 = (tid & 3) * 4;
    const uint32_t sA_u32 = smem_u32(sA);

    int bs[3]; int nb = 0;
    for (int i = 0; i < 3; i++) {
        int bb = w + i * NWRK;
        if (bb < B_) bs[nb++] = bb;
    }

    for (int c = 0; c < T_ / CHUNK; c++) {
        const unsigned need = (unsigned)((c + 1) * CHUNK);
        for (int i = 0; i < nb; i++) {
            const int b = bs[i];
            if (tid == 0) {
                while (ld_acq(&g_flag0[b]) < need) npause();
            }
            __syncthreads();

            const size_t arow = (size_t)b * T_ + (size_t)c * CHUNK;

            // ---- stage A chunk: 64 x 128 floats, coalesced cp.async ----
            for (int idx = tid; idx < 2048; idx += 384) {
                const int m = idx >> 5, c4 = idx & 31;
                cp_async16(sA_u32 + (uint32_t)(m * APAD + c4 * 4) * 4,
                           g_y0 + (arow + m) * H_ + c4 * 4);
            }
            cp_commit(); cp_wait0();
            __syncthreads();

            // ---- 4 n-tiles of 96 ----
            for (int nt = 0; nt < 4; nt++) {
                const int n0 = nt * 96;
                const float* wsrc = W + (size_t)(n0 + gg) * H_ + kq4;
                float4 breg = __ldg((const float4*)wsrc);      // k-block 0
                int buf = 0;
                u64t acc[4][2] = {};

#pragma unroll 1
                for (int kb = 0; kb < 8; kb++) {
                    float* sbb = sB + buf * (16 * BPAD);
                    sbb[(kq4 + 0) * BPAD + gg] = breg.x;
                    sbb[(kq4 + 1) * BPAD + gg] = breg.y;
                    sbb[(kq4 + 2) * BPAD + gg] = breg.z;
                    sbb[(kq4 + 3) * BPAD + gg] = breg.w;
                    if (kb < 7) breg = __ldg((const float4*)(wsrc + (kb + 1) * 16));
                    __syncthreads();                           // one bar / k-block

                    const float* a0p = sA + (ty * 4 + 0) * APAD + kb * 16;
                    const float* a1p = a0p + APAD;
                    const float* a2p = a1p + APAD;
                    const float* a3p = a2p + APAD;
#pragma unroll
                    for (int kk = 0; kk < 16; kk++) {
                        const float4 bv = *(const float4*)(sbb + kk * BPAD + tx * 4);
                        const u64t b01 = pk2(bv.x, bv.y), b23 = pk2(bv.z, bv.w);
                        const float av0 = a0p[kk], av1 = a1p[kk];
                        const float av2 = a2p[kk], av3 = a3p[kk];
                        u64t ai;
                        ai = pk2(av0, av0);
                        acc[0][0] = fma2(ai, b01, acc[0][0]);
                        acc[0][1] = fma2(ai, b23, acc[0][1]);
                        ai = pk2(av1, av1);
                        acc[1][0] = fma2(ai, b01, acc[1][0]);
                        acc[1][1] = fma2(ai, b23, acc[1][1]);
                        ai = pk2(av2, av2);
                        acc[2][0] = fma2(ai, b01, acc[2][0]);
                        acc[2][1] = fma2(ai, b23, acc[2][1]);
                        ai = pk2(av3, av3);
                        acc[3][0] = fma2(ai, b01, acc[3][0]);
                        acc[3][1] = fma2(ai, b23, acc[3][1]);
                    }
                    buf ^= 1;
                }

                const float4 bv = __ldg((const float4*)(bias + n0 + tx * 4));
#pragma unroll
                for (int r = 0; r < 4; r++) {
                    float2 p01 = upk2(acc[r][0]), p23 = upk2(acc[r][1]);
                    float4 o;
                    o.x = p01.x + bv.x; o.y = p01.y + bv.y;
                    o.z = p23.x + bv.z; o.w = p23.y + bv.w;
                    *(float4*)(g_gi1 + (arow + ty * 4 + r) * G_ + n0 + tx * 4) = o;
                }
                __syncthreads();
            }

            __threadfence();
            __syncthreads();
            if (tid == 0) st_rel(&g_flag1[b], need);
        }
    }
}

// ============================================================================
// Scan role (templated). 384 threads, one gate row each; W_hh row in regs;
// h ping-pong in SMEM; 2 barriers/step; gi via 8-deep cp.async ring.
// n-threads carry their own h element in a register (no hcur[j] LDS) and
// defer the y0 STG to the next step's matvec phase (off the phase-2 path).
// Progress flags published every 16 steps with value t (rows < t stored).
// ============================================================================
template <int DO_FC, int STORE_Y>
__device__ __forceinline__ void scan_role(
    int b, const float* __restrict__ Whh, const float* __restrict__ bhh,
    const float* __restrict__ gi_base,
    unsigned* pub_flag, const unsigned* gate_flag,
    const float* __restrict__ fcw, const float* __restrict__ fcb,
    float* __restrict__ out, float* __restrict__ h_final,
    float* __restrict__ pool)
{
    float* sgi  = pool;                       // [GDEPTH][G_]
    float* sh0  = pool + GDEPTH * G_;         // [H_]
    float* sh1  = sh0 + H_;
    float* sh_r = sh1 + H_;
    float* sh_z = sh_r + H_;
    float* sfc  = sh_z + H_;                  // [OUT_*H_]
    float* sfcb = sfc + OUT_ * H_;            // [OUT_]

    const int r = threadIdx.x;       // gate row (r:0-127, z:128-255, n:256-383)

    u64t wp[64];
    {
        const float4* wr = (const float4*)(Whh + (size_t)r * H_);
#pragma unroll
        for (int q = 0; q < 16; q++) {
            float4 wA = __ldg(wr + 2 * q);
            float4 wB = __ldg(wr + 2 * q + 1);
            wp[4 * q + 0] = pk2(wA.x, wA.y);
            wp[4 * q + 1] = pk2(wA.z, wA.w);
            wp[4 * q + 2] = pk2(wB.x, wB.y);
            wp[4 * q + 3] = pk2(wB.z, wB.w);
        }
    }
    const float bias = __ldg(bhh + r);
    if (r < H_) sh0[r] = 0.f;
    if (DO_FC) {
        for (int i = r; i < OUT_ * H_; i += 384) sfc[i] = fcw[i];
        if (r < OUT_) sfcb[r] = fcb[r];
    }

    // ---- gi ring prologue -------------------------------------------------
    const float* gip = gi_base + (size_t)b * T_ * G_ + r;
    const uint32_t sgi_base = smem_u32(sgi + r);
    unsigned known = 0;
    if (gate_flag) {
        do { known = ld_acq(gate_flag); if (known < GDEPTH) npause(); }
        while (known < GDEPTH);
    }
#pragma unroll
    for (int d = 0; d < GDEPTH; d++) {
        cp_async4(sgi_base + (uint32_t)d * (G_ * 4), gip + (size_t)d * G_);
        cp_commit();
    }
    __syncthreads();

    float* hcur = sh0;
    float* hnxt = sh1;
    float* ybase = g_y0 + (size_t)b * T_ * H_ + (r - 256);     // n-threads only
    float* obase = out + (size_t)b * T_ * OUT_;

    const int o   = r >> 3;          // FC output index (r/z threads)
    const int seg = r & 7;
    const float* fcrow = sfc + o * H_ + seg * 16;

    float h_my = 0.f;                // n-thread's own h element (register)
    float y_pend = 0.f;              // deferred y0 store value

    for (int t = 0; t < T_; t++) {
        const int slot = t & (GDEPTH - 1);

        cp_wait7();                                            // stage t landed
        const float gi_cur = sgi[slot * G_ + r];

        // deferred y0 store for step t-1 (issues under the matvec)
        if (STORE_Y && r >= 256 && t > 0)
            ybase[(size_t)(t - 1) * H_] = y_pend;

        // refill slot for step t+GDEPTH (gated on producer if needed)
        const int tp = (t + GDEPTH < T_) ? t + GDEPTH : T_ - 1;
        if (gate_flag && known < (unsigned)(tp + 1)) {
            do { known = ld_acq(gate_flag); if (known < (unsigned)(tp + 1)) npause(); }
            while (known < (unsigned)(tp + 1));
        }
        cp_async4(sgi_base + (uint32_t)slot * (G_ * 4), gip + (size_t)tp * G_);
        cp_commit();

        // ---- phase 1: gh = W_hh[r,:] . h + b ; r,z publish sigmoids --------
        u64t a0 = 0ull, a1 = 0ull, a2 = 0ull, a3 = 0ull;
        const ulonglong2* h2 = (const ulonglong2*)hcur;
#pragma unroll
        for (int q = 0; q < 16; q++) {
            ulonglong2 p0 = h2[2 * q];
            ulonglong2 p1 = h2[2 * q + 1];
            a0 = fma2(wp[4 * q + 0], p0.x, a0);
            a1 = fma2(wp[4 * q + 1], p0.y, a1);
            a2 = fma2(wp[4 * q + 2], p1.x, a2);
            a3 = fma2(wp[4 * q + 3], p1.y, a3);
        }
        float2 sf = upk2(add2(add2(a0, a1), add2(a2, a3)));
        const float gh = sf.x + sf.y + bias;

        if (r < 128)      sh_r[r]       = sigmf(gi_cur + gh);
        else if (r < 256) sh_z[r - 128] = sigmf(gi_cur + gh);
        __syncthreads();                                        // bar 1

        // ---- phase 2: n-threads update h; r/z threads do FC for t-1 --------
        if (r >= 256) {
            const int j = r - 256;
            const float nv = tanhfast(fmaf(sh_r[j], gh, gi_cur));
            const float hnew = fmaf(sh_z[j], h_my - nv, nv);    // (1-z)*n + z*h
            h_my = hnew;
            hnxt[j] = hnew;
            y_pend = hnew;
        } else if (DO_FC && t > 0) {
            const float* hh = hcur + seg * 16;                  // h_{t-1}
            float s = 0.f;
#pragma unroll
            for (int k = 0; k < 16; k++) s = fmaf(fcrow[k], hh[k], s);
            s += __shfl_down_sync(0xffffffffu, s, 4, 8);
            s += __shfl_down_sync(0xffffffffu, s, 2, 8);
            s += __shfl_down_sync(0xffffffffu, s, 1, 8);
            if (seg == 0) obase[(size_t)(t - 1) * OUT_ + o] = s + sfcb[o];
        }

        // publish rows < t (row t-1 was stored during this step's phase 1)
        const bool pub_now = STORE_Y && ((t & 15) == 0) && (t > 0);
        if (pub_now) __threadfence();
        __syncthreads();                                        // bar 2
        if (pub_now && r == 0) st_rel(pub_flag, (unsigned)t);

        float* tmp = hcur; hcur = hnxt; hnxt = tmp;
    }

    // tail: last y0 row + final flag publish
    if (STORE_Y) {
        if (r >= 256) ybase[(size_t)(T_ - 1) * H_] = y_pend;
        __threadfence();
        __syncthreads();
        if (r == 0) st_rel(pub_flag, (unsigned)T_);
    }

    // final-step FC (h_{T-1} sits in hcur after the last swap)
    if (DO_FC && r < 256) {
        const float* hh = hcur + seg * 16;
        float s = 0.f;
#pragma unroll
        for (int k = 0; k < 16; k++) s = fmaf(fcrow[k], hh[k], s);
        s += __shfl_down_sync(0xffffffffu, s, 4, 8);
        s += __shfl_down_sync(0xffffffffu, s, 2, 8);
        s += __shfl_down_sync(0xffffffffu, s, 1, 8);
        if (seg == 0) obase[(size_t)(T_ - 1) * OUT_ + o] = s + sfcb[o];
    }
    if (r >= 256) h_final[(size_t)b * H_ + (r - 256)] = h_my;
}

// ============================================================================
// Fused persistent kernel: 152 CTAs (GB300 has 152 SMs; all wave-1 resident).
//   CTA 0..63    : layer-0 scan (batch = bid)
//   CTA 64..87   : gi1 GEMM workers (batches w, w+24 [, w+48])
//   CTA 88..151  : layer-1 scan + FC (batch = bid-88)
// ============================================================================
__global__ void __launch_bounds__(384, 1) k_fused(
    const float* __restrict__ Whh0, const float* __restrict__ bhh0,
    const float* __restrict__ Whh1, const float* __restrict__ bhh1,
    const float* __restrict__ Wih1, const float* __restrict__ bih1,
    const float* __restrict__ fcw,  const float* __restrict__ fcb,
    float* __restrict__ out, float* __restrict__ hout)
{
    __shared__ __align__(16) float pool[POOLF];

    const int bid = blockIdx.x;

    if (bid < B_) {
        scan_role<0, 1>(bid, Whh0, bhh0, g_gi,
                        /*pub=*/&g_flag0[bid], /*gate=*/nullptr,
                        fcw, fcb, out, hout, pool);
    } else if (bid < B_ + NWRK) {
        worker_role(bid - B_, Wih1, bih1, pool);
    } else {
        const int b = bid - (B_ + NWRK);
        scan_role<1, 0>(b, Whh1, bhh1, g_gi1,
                        /*pub=*/nullptr, /*gate=*/&g_flag1[b],
                        fcw, fcb, out, hout + (size_t)B_ * H_, pool);
    }
}

// ============================================================================
extern "C" void kernel_launch(void* const* d_in, const int* in_sizes, int n_in,
                              void* d_out, int out_size) {
    const float* x    = (const float*)d_in[0];
    const float* Wih0 = (const float*)d_in[1];
    const float* Whh0 = (const float*)d_in[2];
    const float* bih0 = (const float*)d_in[3];
    const float* bhh0 = (const float*)d_in[4];
    const float* Wih1 = (const float*)d_in[5];
    const float* Whh1 = (const float*)d_in[6];
    const float* bih1 = (const float*)d_in[7];
    const float* bhh1 = (const float*)d_in[8];
    const float* fcw  = (const float*)d_in[9];
    const float* fcb  = (const float*)d_in[10];

    float* out  = (float*)d_out;                       // [B,T,OUT]
    float* hout = out + (size_t)B_ * T_ * OUT_;        // [2,B,H] stacked after out

    // K1: layer-0 input projection + flag reset (graph-ordered before fused)
    k1_gi0<<<BT_ / 64, 384>>>(x, Wih0, bih0);
    // Fused pipeline: L0 scan || gi1 GEMM || L1 scan+FC
    k_fused<<<B_ + NWRK + B_, 384>>>(Whh0, bhh0, Whh1, bhh1, Wih1, bih1,
                                     fcw, fcb, out, hout);
}

// round 14
// speedup vs baseline: 1.0066x; 1.0066x over previous
#include <cuda_runtime.h>
#include <cuda_bf16.h>
#include <cstdint>

#define B_   64
#define T_   4096
#define IN_  32
#define H_   128
#define G_   384
#define OUT_ 32
#define BT_  (B_ * T_)
#define GDEPTH 8          // cp.async gi ring depth
#define NWRK 24           // gi1 GEMM worker CTAs (grid 152 = GB300 SM count)
#define CHUNK 64          // pipeline chunk (steps)

// worker SMEM geometry
#define APAD 132          // A row stride (floats): 64 rows x 132
#define POOLF (64 * APAD) // 8448 floats = 33.8 KB; >= scan pool (7712)

// ---------------- scratch (static __device__; allocation-free rule) ----------
__device__ float g_gi [(size_t)BT_ * G_];    // layer-0 gate pre-activations
__device__ float g_gi1[(size_t)BT_ * G_];    // layer-1 gate pre-activations
__device__ float g_y0 [(size_t)BT_ * H_];    // layer-0 outputs
__device__ unsigned g_flag0[B_];             // y0 rows ready per batch
__device__ unsigned g_flag1[B_];             // gi1 rows ready per batch

typedef unsigned long long u64t;

// ---------------- packed f32x2 helpers (sm_103a FFMA2 via PTX) ---------------
__device__ __forceinline__ u64t pk2(float a, float b) {
    u64t r; asm("mov.b64 %0, {%1,%2};" : "=l"(r) : "f"(a), "f"(b)); return r;
}
__device__ __forceinline__ u64t fma2(u64t a, u64t b, u64t c) {
    u64t d; asm("fma.rn.f32x2 %0, %1, %2, %3;" : "=l"(d) : "l"(a), "l"(b), "l"(c)); return d;
}
__device__ __forceinline__ u64t add2(u64t a, u64t b) {
    u64t d; asm("add.rn.f32x2 %0, %1, %2;" : "=l"(d) : "l"(a), "l"(b)); return d;
}
__device__ __forceinline__ float2 upk2(u64t a) {
    float2 f; asm("mov.b64 {%0,%1}, %2;" : "=f"(f.x), "=f"(f.y) : "l"(a)); return f;
}

__device__ __forceinline__ float sigmf(float x) {
    return __fdividef(1.f, 1.f + __expf(-x));
}
__device__ __forceinline__ float tanhfast(float x) {
    float e = __expf(-2.f * x);
    return __fdividef(1.f - e, 1.f + e);
}

__device__ __forceinline__ uint32_t smem_u32(const void* p) {
    uint32_t a;
    asm("{ .reg .u64 t; cvta.to.shared.u64 t, %1; cvt.u32.u64 %0, t; }"
        : "=r"(a) : "l"(p));
    return a;
}
__device__ __forceinline__ void cp_async4(uint32_t saddr, const float* gaddr) {
    asm volatile("cp.async.ca.shared.global [%0], [%1], 4;" :: "r"(saddr), "l"(gaddr));
}
__device__ __forceinline__ void cp_async16(uint32_t saddr, const float* gaddr) {
    asm volatile("cp.async.ca.shared.global [%0], [%1], 16;" :: "r"(saddr), "l"(gaddr));
}
__device__ __forceinline__ void cp_commit() { asm volatile("cp.async.commit_group;"); }
__device__ __forceinline__ void cp_wait7()  { asm volatile("cp.async.wait_group 7;"); }
__device__ __forceinline__ void cp_wait0()  { asm volatile("cp.async.wait_group 0;"); }

__device__ __forceinline__ unsigned ld_acq(const unsigned* p) {
    unsigned v;
    asm volatile("ld.acquire.gpu.global.u32 %0, [%1];" : "=r"(v) : "l"(p) : "memory");
    return v;
}
__device__ __forceinline__ void st_rel(unsigned* p, unsigned v) {
    asm volatile("st.release.gpu.global.u32 [%0], %1;" :: "l"(p), "r"(v) : "memory");
}
__device__ __forceinline__ void npause() {
    asm volatile("nanosleep.u32 200;");
}

// ============================================================================
// K1: gi0 = x @ W_ih0^T + b_ih0 (64 rows/CTA; also resets flags each replay)
// ============================================================================
__global__ void k1_gi0(const float* __restrict__ x,
                       const float* __restrict__ W,
                       const float* __restrict__ b) {
    __shared__ __align__(16) float sx[64 * IN_];
    const int tid = threadIdx.x;                 // gate row 0..383
    const size_t bt0 = (size_t)blockIdx.x * 64;

    if (blockIdx.x == 0 && tid < 2 * B_) {
        if (tid < B_) g_flag0[tid] = 0; else g_flag1[tid - B_] = 0;
    }

    for (int i = tid; i < 64 * IN_ / 4; i += 384)
        ((float4*)sx)[i] = ((const float4*)(x + bt0 * IN_))[i];

    u64t wp[16];
    {
        const float4* wr = (const float4*)(W + (size_t)tid * IN_);
#pragma unroll
        for (int q = 0; q < 8; q++) {
            float4 w4 = __ldg(wr + q);
            wp[2 * q]     = pk2(w4.x, w4.y);
            wp[2 * q + 1] = pk2(w4.z, w4.w);
        }
    }
    const float bias = __ldg(b + tid);
    __syncthreads();

#pragma unroll 4
    for (int row = 0; row < 64; row++) {
        const ulonglong2* xr = (const ulonglong2*)(sx + row * IN_);
        u64t a0 = 0ull, a1 = 0ull;
#pragma unroll
        for (int q = 0; q < 8; q++) {
            ulonglong2 xp = xr[q];
            a0 = fma2(wp[2 * q],     xp.x, a0);
            a1 = fma2(wp[2 * q + 1], xp.y, a1);
        }
        float2 s = upk2(add2(a0, a1));
        g_gi[(bt0 + row) * G_ + tid] = s.x + s.y + bias;
    }
}

// ============================================================================
// Worker role (scan-style): each thread owns W_ih1 row `tid` in registers;
// per 64-step chunk: stage y0 chunk once via cp.async, then 64 broadcast
// matvecs (32 LDS.128 + 64 fma2 each) with NO inner barriers/B-staging.
// Output STG coalesced across tid.
// ============================================================================
__device__ __forceinline__ void worker_role(
    int w, const float* __restrict__ W, const float* __restrict__ bias,
    float* __restrict__ pool)
{
    float* sA = pool;                        // 64 x APAD (y0 chunk)
    const int tid = threadIdx.x;             // gate row 0..383
    const uint32_t sA_u32 = smem_u32(sA);

    u64t wp[64];
    {
        const float4* wr = (const float4*)(W + (size_t)tid * H_);
#pragma unroll
        for (int q = 0; q < 16; q++) {
            float4 wA = __ldg(wr + 2 * q);
            float4 wB = __ldg(wr + 2 * q + 1);
            wp[4 * q + 0] = pk2(wA.x, wA.y);
            wp[4 * q + 1] = pk2(wA.z, wA.w);
            wp[4 * q + 2] = pk2(wB.x, wB.y);
            wp[4 * q + 3] = pk2(wB.z, wB.w);
        }
    }
    const float bias_t = __ldg(bias + tid);

    int bs[3]; int nb = 0;
    for (int i = 0; i < 3; i++) {
        int bb = w + i * NWRK;
        if (bb < B_) bs[nb++] = bb;
    }

    for (int c = 0; c < T_ / CHUNK; c++) {
        const unsigned need = (unsigned)((c + 1) * CHUNK);
        for (int i = 0; i < nb; i++) {
            const int b = bs[i];
            if (tid == 0) {
                while (ld_acq(&g_flag0[b]) < need) npause();
            }
            __syncthreads();   // also isolates prior compute reads from restage

            const size_t arow = (size_t)b * T_ + (size_t)c * CHUNK;

            // ---- stage y0 chunk: 64 x 128 floats, coalesced cp.async ----
            for (int idx = tid; idx < 2048; idx += 384) {
                const int m = idx >> 5, c4 = idx & 31;
                cp_async16(sA_u32 + (uint32_t)(m * APAD + c4 * 4) * 4,
                           g_y0 + (arow + m) * H_ + c4 * 4);
            }
            cp_commit(); cp_wait0();
            __syncthreads();

            // ---- 64 matvecs: gi1[m][tid] = W_row . y0[m] + b ----
            float* dst = g_gi1 + arow * G_ + tid;
#pragma unroll 1
            for (int m = 0; m < CHUNK; m++) {
                const ulonglong2* h2 = (const ulonglong2*)(sA + m * APAD);
                u64t a0 = 0ull, a1 = 0ull, a2 = 0ull, a3 = 0ull;
#pragma unroll
                for (int q = 0; q < 16; q++) {
                    ulonglong2 p0 = h2[2 * q];
                    ulonglong2 p1 = h2[2 * q + 1];
                    a0 = fma2(wp[4 * q + 0], p0.x, a0);
                    a1 = fma2(wp[4 * q + 1], p0.y, a1);
                    a2 = fma2(wp[4 * q + 2], p1.x, a2);
                    a3 = fma2(wp[4 * q + 3], p1.y, a3);
                }
                float2 sf = upk2(add2(add2(a0, a1), add2(a2, a3)));
                dst[(size_t)m * G_] = sf.x + sf.y + bias_t;
            }

            __threadfence();
            __syncthreads();
            if (tid == 0) st_rel(&g_flag1[b], need);
        }
    }
}

// ============================================================================
// Scan role (templated, R13). 384 threads, one gate row each; W_hh row in
// regs; h ping-pong in SMEM; 2 barriers/step; gi via 8-deep cp.async ring.
// n-threads carry h in a register; y0 STG deferred to next step's matvec.
// ============================================================================
template <int DO_FC, int STORE_Y>
__device__ __forceinline__ void scan_role(
    int b, const float* __restrict__ Whh, const float* __restrict__ bhh,
    const float* __restrict__ gi_base,
    unsigned* pub_flag, const unsigned* gate_flag,
    const float* __restrict__ fcw, const float* __restrict__ fcb,
    float* __restrict__ out, float* __restrict__ h_final,
    float* __restrict__ pool)
{
    float* sgi  = pool;                       // [GDEPTH][G_]
    float* sh0  = pool + GDEPTH * G_;         // [H_]
    float* sh1  = sh0 + H_;
    float* sh_r = sh1 + H_;
    float* sh_z = sh_r + H_;
    float* sfc  = sh_z + H_;                  // [OUT_*H_]
    float* sfcb = sfc + OUT_ * H_;            // [OUT_]

    const int r = threadIdx.x;       // gate row (r:0-127, z:128-255, n:256-383)

    u64t wp[64];
    {
        const float4* wr = (const float4*)(Whh + (size_t)r * H_);
#pragma unroll
        for (int q = 0; q < 16; q++) {
            float4 wA = __ldg(wr + 2 * q);
            float4 wB = __ldg(wr + 2 * q + 1);
            wp[4 * q + 0] = pk2(wA.x, wA.y);
            wp[4 * q + 1] = pk2(wA.z, wA.w);
            wp[4 * q + 2] = pk2(wB.x, wB.y);
            wp[4 * q + 3] = pk2(wB.z, wB.w);
        }
    }
    const float bias = __ldg(bhh + r);
    if (r < H_) sh0[r] = 0.f;
    if (DO_FC) {
        for (int i = r; i < OUT_ * H_; i += 384) sfc[i] = fcw[i];
        if (r < OUT_) sfcb[r] = fcb[r];
    }

    // ---- gi ring prologue -------------------------------------------------
    const float* gip = gi_base + (size_t)b * T_ * G_ + r;
    const uint32_t sgi_base = smem_u32(sgi + r);
    unsigned known = 0;
    if (gate_flag) {
        do { known = ld_acq(gate_flag); if (known < GDEPTH) npause(); }
        while (known < GDEPTH);
    }
#pragma unroll
    for (int d = 0; d < GDEPTH; d++) {
        cp_async4(sgi_base + (uint32_t)d * (G_ * 4), gip + (size_t)d * G_);
        cp_commit();
    }
    __syncthreads();

    float* hcur = sh0;
    float* hnxt = sh1;
    float* ybase = g_y0 + (size_t)b * T_ * H_ + (r - 256);     // n-threads only
    float* obase = out + (size_t)b * T_ * OUT_;

    const int o   = r >> 3;          // FC output index (r/z threads)
    const int seg = r & 7;
    const float* fcrow = sfc + o * H_ + seg * 16;

    float h_my = 0.f;                // n-thread's own h element (register)
    float y_pend = 0.f;              // deferred y0 store value

    for (int t = 0; t < T_; t++) {
        const int slot = t & (GDEPTH - 1);

        cp_wait7();                                            // stage t landed
        const float gi_cur = sgi[slot * G_ + r];

        // deferred y0 store for step t-1 (issues under the matvec)
        if (STORE_Y && r >= 256 && t > 0)
            ybase[(size_t)(t - 1) * H_] = y_pend;

        // refill slot for step t+GDEPTH (gated on producer if needed)
        const int tp = (t + GDEPTH < T_) ? t + GDEPTH : T_ - 1;
        if (gate_flag && known < (unsigned)(tp + 1)) {
            do { known = ld_acq(gate_flag); if (known < (unsigned)(tp + 1)) npause(); }
            while (known < (unsigned)(tp + 1));
        }
        cp_async4(sgi_base + (uint32_t)slot * (G_ * 4), gip + (size_t)tp * G_);
        cp_commit();

        // ---- phase 1: gh = W_hh[r,:] . h + b ; r,z publish sigmoids --------
        u64t a0 = 0ull, a1 = 0ull, a2 = 0ull, a3 = 0ull;
        const ulonglong2* h2 = (const ulonglong2*)hcur;
#pragma unroll
        for (int q = 0; q < 16; q++) {
            ulonglong2 p0 = h2[2 * q];
            ulonglong2 p1 = h2[2 * q + 1];
            a0 = fma2(wp[4 * q + 0], p0.x, a0);
            a1 = fma2(wp[4 * q + 1], p0.y, a1);
            a2 = fma2(wp[4 * q + 2], p1.x, a2);
            a3 = fma2(wp[4 * q + 3], p1.y, a3);
        }
        float2 sf = upk2(add2(add2(a0, a1), add2(a2, a3)));
        const float gh = sf.x + sf.y + bias;

        if (r < 128)      sh_r[r]       = sigmf(gi_cur + gh);
        else if (r < 256) sh_z[r - 128] = sigmf(gi_cur + gh);
        __syncthreads();                                        // bar 1

        // ---- phase 2: n-threads update h; r/z threads do FC for t-1 --------
        if (r >= 256) {
            const int j = r - 256;
            const float nv = tanhfast(fmaf(sh_r[j], gh, gi_cur));
            const float hnew = fmaf(sh_z[j], h_my - nv, nv);    // (1-z)*n + z*h
            h_my = hnew;
            hnxt[j] = hnew;
            y_pend = hnew;
        } else if (DO_FC && t > 0) {
            const float* hh = hcur + seg * 16;                  // h_{t-1}
            float s = 0.f;
#pragma unroll
            for (int k = 0; k < 16; k++) s = fmaf(fcrow[k], hh[k], s);
            s += __shfl_down_sync(0xffffffffu, s, 4, 8);
            s += __shfl_down_sync(0xffffffffu, s, 2, 8);
            s += __shfl_down_sync(0xffffffffu, s, 1, 8);
            if (seg == 0) obase[(size_t)(t - 1) * OUT_ + o] = s + sfcb[o];
        }

        // publish rows < t (row t-1 was stored during this step's phase 1)
        const bool pub_now = STORE_Y && ((t & 15) == 0) && (t > 0);
        if (pub_now) __threadfence();
        __syncthreads();                                        // bar 2
        if (pub_now && r == 0) st_rel(pub_flag, (unsigned)t);

        float* tmp = hcur; hcur = hnxt; hnxt = tmp;
    }

    // tail: last y0 row + final flag publish
    if (STORE_Y) {
        if (r >= 256) ybase[(size_t)(T_ - 1) * H_] = y_pend;
        __threadfence();
        __syncthreads();
        if (r == 0) st_rel(pub_flag, (unsigned)T_);
    }

    // final-step FC (h_{T-1} sits in hcur after the last swap)
    if (DO_FC && r < 256) {
        const float* hh = hcur + seg * 16;
        float s = 0.f;
#pragma unroll
        for (int k = 0; k < 16; k++) s = fmaf(fcrow[k], hh[k], s);
        s += __shfl_down_sync(0xffffffffu, s, 4, 8);
        s += __shfl_down_sync(0xffffffffu, s, 2, 8);
        s += __shfl_down_sync(0xffffffffu, s, 1, 8);
        if (seg == 0) obase[(size_t)(T_ - 1) * OUT_ + o] = s + sfcb[o];
    }
    if (r >= 256) h_final[(size_t)b * H_ + (r - 256)] = h_my;
}

// ============================================================================
// Fused persistent kernel: 152 CTAs (GB300 has 152 SMs; all wave-1 resident).
//   CTA 0..63    : layer-0 scan (batch = bid)
//   CTA 64..87   : gi1 workers (batches w, w+24 [, w+48])
//   CTA 88..151  : layer-1 scan + FC (batch = bid-88)
// ============================================================================
__global__ void __launch_bounds__(384, 1) k_fused(
    const float* __restrict__ Whh0, const float* __restrict__ bhh0,
    const float* __restrict__ Whh1, const float* __restrict__ bhh1,
    const float* __restrict__ Wih1, const float* __restrict__ bih1,
    const float* __restrict__ fcw,  const float* __restrict__ fcb,
    float* __restrict__ out, float* __restrict__ hout)
{
    __shared__ __align__(16) float pool[POOLF];

    const int bid = blockIdx.x;

    if (bid < B_) {
        scan_role<0, 1>(bid, Whh0, bhh0, g_gi,
                        /*pub=*/&g_flag0[bid], /*gate=*/nullptr,
                        fcw, fcb, out, hout, pool);
    } else if (bid < B_ + NWRK) {
        worker_role(bid - B_, Wih1, bih1, pool);
    } else {
        const int b = bid - (B_ + NWRK);
        scan_role<1, 0>(b, Whh1, bhh1, g_gi1,
                        /*pub=*/nullptr, /*gate=*/&g_flag1[b],
                        fcw, fcb, out, hout + (size_t)B_ * H_, pool);
    }
}

// ============================================================================
extern "C" void kernel_launch(void* const* d_in, const int* in_sizes, int n_in,
                              void* d_out, int out_size) {
    const float* x    = (const float*)d_in[0];
    const float* Wih0 = (const float*)d_in[1];
    const float* Whh0 = (const float*)d_in[2];
    const float* bih0 = (const float*)d_in[3];
    const float* bhh0 = (const float*)d_in[4];
    const float* Wih1 = (const float*)d_in[5];
    const float* Whh1 = (const float*)d_in[6];
    const float* bih1 = (const float*)d_in[7];
    const float* bhh1 = (const float*)d_in[8];
    const float* fcw  = (const float*)d_in[9];
    const float* fcb  = (const float*)d_in[10];

    float* out  = (float*)d_out;                       // [B,T,OUT]
    float* hout = out + (size_t)B_ * T_ * OUT_;        // [2,B,H] stacked after out

    // K1: layer-0 input projection + flag reset (graph-ordered before fused)
    k1_gi0<<<BT_ / 64, 384>>>(x, Wih0, bih0);
    // Fused pipeline: L0 scan || gi1 workers || L1 scan+FC
    k_fused<<<B_ + NWRK + B_, 384>>>(Whh0, bhh0, Whh1, bhh1, Wih1, bih1,
                                     fcw, fcb, out, hout);
}